// round 16
// baseline (speedup 1.0000x reference)
#include <cuda_runtime.h>
#include <cuda_fp16.h>
#include <math.h>
#include <cstdint>

#define BSROWS 8192
#define SEQ    2048
#define DIM    1024
#define NH     16
#define DFF    4096

// ---------------------------------------------------------------------------
// Scratch (device globals)
// ---------------------------------------------------------------------------
__device__ __half g_lnh  [8388608];    // LN output (reused LN1/LN2)
__device__ __half g_vh   [8388608];    // v = LN1@W_in + b_in
__device__ __half g_a2h  [1048576];    // A rearranged [h][j*32+i][p]
__device__ __half g_Mh   [134217728];  // M[h][bs][j*32+i]   (268MB)
__device__ __half g_hsh  [4194304];    // recurrence out [bs][H*DH]
__device__ float  g_x2   [8388608];    // x + hs@W_out + b_out (fp32 residual)
__device__ __half g_ffnh [33554432];   // GELU(LN2@W1+b1)
__device__ __half g_winh [1048576];    // W_in^T  [1024][1024]
__device__ __half g_wouth[524288];     // W_out^T [1024][512]
__device__ __half g_w1h  [4194304];    // W1^T    [4096][1024]
__device__ __half g_w2h  [4194304];    // W2^T    [1024][4096]

// ---------------------------------------------------------------------------
// Helpers
// ---------------------------------------------------------------------------
__device__ __forceinline__ uint32_t smem_u32(const void* p) {
    return (uint32_t)__cvta_generic_to_shared(p);
}
__device__ __forceinline__ float gelu_exact(float x) {
    return 0.5f * x * (1.0f + erff(x * 0.70710678118654752f));
}
__device__ __forceinline__ void cp16(uint32_t dst, const void* src) {
    asm volatile("cp.async.cg.shared.global [%0], [%1], 16;" :: "r"(dst), "l"(src));
}
__device__ __forceinline__ float tanh_fast(float x) {
    float r;
    asm("tanh.approx.f32 %0, %1;" : "=f"(r) : "f"(x));
    return r;
}
__device__ __forceinline__ void mma_f16(float* d, const uint32_t* a, const uint32_t* b) {
    asm volatile(
        "mma.sync.aligned.m16n8k16.row.col.f32.f16.f16.f32 "
        "{%0,%1,%2,%3}, {%4,%5,%6,%7}, {%8,%9}, {%0,%1,%2,%3};"
        : "+f"(d[0]), "+f"(d[1]), "+f"(d[2]), "+f"(d[3])
        : "r"(a[0]), "r"(a[1]), "r"(a[2]), "r"(a[3]),
          "r"(b[0]), "r"(b[1]));
}
__device__ __forceinline__ void ldsm4(uint32_t& r0, uint32_t& r1, uint32_t& r2,
                                      uint32_t& r3, uint32_t addr) {
    asm volatile("ldmatrix.sync.aligned.m8n8.x4.shared.b16 {%0,%1,%2,%3}, [%4];"
                 : "=r"(r0), "=r"(r1), "=r"(r2), "=r"(r3) : "r"(addr));
}

// ---------------------------------------------------------------------------
// prep: A[h][i][p][j] -> a2h[h][j*32+i][p]  (fp16)
// ---------------------------------------------------------------------------
__global__ void prep_A_kernel(const float* __restrict__ A, __half* __restrict__ A2) {
    int idx = blockIdx.x * 256 + threadIdx.x;
    int j = idx & 31;
    int p = (idx >> 5) & 63;
    int i = (idx >> 11) & 31;
    int h = idx >> 16;
    A2[(size_t)h * 65536 + (size_t)(j * 32 + i) * 64 + p] = __float2half(A[idx]);
}

// ---------------------------------------------------------------------------
// Merged weight transposes (fp32 [R][C] -> fp16 [C][R]).
// ---------------------------------------------------------------------------
__device__ __forceinline__ void ttile(const float* __restrict__ in,
                                      __half* __restrict__ out,
                                      int R, int C, int bx, int by) {
    __shared__ float t[32][33];
    int tx = threadIdx.x, ty = threadIdx.y;
    int x0 = bx * 32, y0 = by * 32;
#pragma unroll
    for (int j = 0; j < 32; j += 8)
        t[ty + j][tx] = in[(size_t)(y0 + ty + j) * C + x0 + tx];
    __syncthreads();
#pragma unroll
    for (int j = 0; j < 32; j += 8)
        out[(size_t)(x0 + ty + j) * R + y0 + tx] = __float2half(t[tx][ty + j]);
}

__global__ void tconv_all_kernel(const float* __restrict__ W1, __half* __restrict__ w1h,
                                 const float* __restrict__ W2, __half* __restrict__ w2h,
                                 const float* __restrict__ Wi, __half* __restrict__ wih,
                                 const float* __restrict__ Wo, __half* __restrict__ woh)
{
    int t = blockIdx.x;
    if (t < 4096)        ttile(W1, w1h, 1024, 4096, t & 127, t >> 7);
    else if (t < 8192)   { t -= 4096; ttile(W2, w2h, 4096, 1024, t & 31, t >> 5); }
    else if (t < 9216)   { t -= 8192; ttile(Wi, wih, 1024, 1024, t & 31, t >> 5); }
    else                 { t -= 9216; ttile(Wo, woh, 512, 1024, t & 31, t >> 5); }
}

// ---------------------------------------------------------------------------
// LayerNorm (fp32 in, fp16 out).
// ---------------------------------------------------------------------------
__global__ void ln_h_kernel(const float* __restrict__ x, const float* __restrict__ g,
                            const float* __restrict__ b, __half* __restrict__ y) {
    int row = blockIdx.x;
    int tid = threadIdx.x;
    const float* xr = x + (size_t)row * DIM;
    float v[4];
    float s = 0.f, sq = 0.f;
#pragma unroll
    for (int i = 0; i < 4; i++) {
        v[i] = xr[tid + i * 256];
        s  += v[i];
        sq += v[i] * v[i];
    }
#pragma unroll
    for (int o = 16; o > 0; o >>= 1) {
        s  += __shfl_xor_sync(0xffffffffu, s,  o);
        sq += __shfl_xor_sync(0xffffffffu, sq, o);
    }
    __shared__ float ss[8], sqq[8];
    int w = tid >> 5, l = tid & 31;
    if (l == 0) { ss[w] = s; sqq[w] = sq; }
    __syncthreads();
    if (w == 0) {
        s  = (l < 8) ? ss[l]  : 0.f;
        sq = (l < 8) ? sqq[l] : 0.f;
#pragma unroll
        for (int o = 4; o > 0; o >>= 1) {
            s  += __shfl_xor_sync(0xffffffffu, s,  o);
            sq += __shfl_xor_sync(0xffffffffu, sq, o);
        }
        if (l == 0) { ss[0] = s; sqq[0] = sq; }
    }
    __syncthreads();
    s = ss[0]; sq = sqq[0];
    float mean = s * (1.0f / DIM);
    float var  = sq * (1.0f / DIM) - mean * mean;
    float rstd = rsqrtf(var + 1e-5f);
    __half* yr = y + (size_t)row * DIM;
#pragma unroll
    for (int i = 0; i < 4; i++) {
        int c = tid + i * 256;
        yr[c] = __float2half((v[i] - mean) * rstd * g[c] + b[c]);
    }
}

// ---------------------------------------------------------------------------
// fp16 warp-MMA GEMM — R15 configuration (best measured): 512 threads,
// warp tile 32x32, 2 CTAs/SM (64 regs), CTA tile 128x128, BK=32, 3-stage
// cp.async, ldmatrix fragments, mma.m16n8k16, fp32 accumulate.
// SMEM [3][128][40] halves each for A and B (stride 40 -> conflict-free).
// EPI: bit0=bias, bit1=residual(float), bit2=gelu.  OT: __half or float.
// ---------------------------------------------------------------------------
#define HSMEM_BYTES 61440

template <int EPI, typename OT>
__global__ void __launch_bounds__(512, 2) hgemm(
    const __half* __restrict__ A, const __half* __restrict__ BT, OT* __restrict__ C,
    const float* __restrict__ bias, const float* __restrict__ res,
    int K, int lda, int ldb, int ldc,
    size_t batchA, size_t batchB, size_t batchC)
{
    extern __shared__ __half hsm[];
    __half* As = hsm;            // [3][128][40]
    __half* Bs = hsm + 15360;    // [3][128][40]

    A  += (size_t)blockIdx.z * batchA;
    BT += (size_t)blockIdx.z * batchB;
    C  += (size_t)blockIdx.z * batchC;

    const int tid = threadIdx.x;
    const int m0 = blockIdx.y * 128, n0 = blockIdx.x * 128;
    const int wid = tid >> 5, lane = tid & 31;
    const int wm = (wid >> 2) * 32;     // 0,32,64,96
    const int wn = (wid & 3) * 32;      // 0,32,64,96
    const int gq = lane >> 2, tg = lane & 3;

    const uint32_t sA = smem_u32(As);
    const uint32_t sB = smem_u32(Bs);

    // gmem->smem: 4 threads per 64B row (1 cp16 each)
    const int row = tid >> 2, seg = tid & 3;

    auto loadA = [&](int st, int k0) {
        const __half* src = A + (size_t)(m0 + row) * lda + k0 + seg * 8;
        uint32_t dst = sA + (uint32_t)st * 10240 + (uint32_t)row * 80 + (uint32_t)seg * 16;
        cp16(dst, src);
    };
    auto loadB = [&](int st, int k0) {
        const __half* src = BT + (size_t)(n0 + row) * ldb + k0 + seg * 8;
        uint32_t dst = sB + (uint32_t)st * 10240 + (uint32_t)row * 80 + (uint32_t)seg * 16;
        cp16(dst, src);
    };

    // ldmatrix per-lane byte offsets (within a stage)
    const int arow_l = (lane & 7) | (((lane >> 3) & 1) << 3);  // 0..15
    const int aseg   = lane >> 4;                              // 0/1 (k half)
    const uint32_t aoffB = (uint32_t)(wm + arow_l) * 80 + (uint32_t)aseg * 16;
    const int brow_l = (lane & 7) + ((lane >> 4) << 3);        // 0..15
    const int bseg   = (lane >> 3) & 1;                        // 0/1 (k half)
    const uint32_t boffB = (uint32_t)(wn + brow_l) * 80 + (uint32_t)bseg * 16;

    float acc[2][4][4];
#pragma unroll
    for (int mi = 0; mi < 2; mi++)
#pragma unroll
        for (int ni = 0; ni < 4; ni++)
#pragma unroll
            for (int q = 0; q < 4; q++) acc[mi][ni][q] = 0.f;

    const int KT = K >> 5;
    loadA(0, 0);  loadB(0, 0);
    asm volatile("cp.async.commit_group;");
    loadA(1, 32); loadB(1, 32);
    asm volatile("cp.async.commit_group;");

    for (int kt = 0; kt < KT; ++kt) {
        const int buf = kt % 3;
        asm volatile("cp.async.wait_group 1;");
        __syncthreads();
        if (kt + 2 < KT) {
            const int st = (kt + 2) % 3;
            loadA(st, (kt + 2) * 32);
            loadB(st, (kt + 2) * 32);
        }
        asm volatile("cp.async.commit_group;");

        const uint32_t aB = sA + (uint32_t)buf * 10240 + aoffB;
        const uint32_t bB = sB + (uint32_t)buf * 10240 + boffB;
#pragma unroll
        for (int kk = 0; kk < 32; kk += 16) {
            uint32_t a[2][4], b[4][2];
#pragma unroll
            for (int mi = 0; mi < 2; mi++)
                ldsm4(a[mi][0], a[mi][1], a[mi][2], a[mi][3],
                      aB + (uint32_t)mi * (16 * 80) + (uint32_t)kk * 2);
#pragma unroll
            for (int p = 0; p < 2; p++)
                ldsm4(b[2 * p][0], b[2 * p][1], b[2 * p + 1][0], b[2 * p + 1][1],
                      bB + (uint32_t)p * (16 * 80) + (uint32_t)kk * 2);
#pragma unroll
            for (int mi = 0; mi < 2; mi++)
#pragma unroll
                for (int ni = 0; ni < 4; ni++)
                    mma_f16(acc[mi][ni], a[mi], b[ni]);
        }
    }

    // epilogue
#pragma unroll
    for (int mi = 0; mi < 2; mi++) {
        const int r0 = m0 + wm + mi * 16 + gq;
#pragma unroll
        for (int ni = 0; ni < 4; ni++) {
            const int c = n0 + wn + ni * 8 + 2 * tg;
            float2 v01 = make_float2(acc[mi][ni][0], acc[mi][ni][1]);
            float2 v23 = make_float2(acc[mi][ni][2], acc[mi][ni][3]);
            if (EPI & 1) {
                float2 bv = *(const float2*)(bias + c);
                v01.x += bv.x; v01.y += bv.y;
                v23.x += bv.x; v23.y += bv.y;
            }
            if (EPI & 4) {
                v01.x = gelu_exact(v01.x); v01.y = gelu_exact(v01.y);
                v23.x = gelu_exact(v23.x); v23.y = gelu_exact(v23.y);
            }
            size_t off0 = (size_t)r0 * ldc + c;
            size_t off1 = (size_t)(r0 + 8) * ldc + c;
            if (EPI & 2) {
                float2 q0 = *(const float2*)(res + off0);
                float2 q1 = *(const float2*)(res + off1);
                v01.x += q0.x; v01.y += q0.y;
                v23.x += q1.x; v23.y += q1.y;
            }
            if constexpr (sizeof(OT) == 2) {
                *(__half2*)((__half*)C + off0) = __floats2half2_rn(v01.x, v01.y);
                *(__half2*)((__half*)C + off1) = __floats2half2_rn(v23.x, v23.y);
            } else {
                *(float2*)((float*)C + off0) = v01;
                *(float2*)((float*)C + off1) = v23;
            }
        }
    }
}

// ---------------------------------------------------------------------------
// Sequential MPS recurrence — R10 skeleton with vectorized row loads:
// the 16 scalar LDS.32 half2 reads per step become 4 LDS.128 (uint4),
// cutting ~12 issue slots from the single-warp serial loop. Arithmetic
// order identical to R10. One warp per (b,h) chain; 8-stage cp.async
// prefetch; h fp32 in double-buffered smem; tanh.approx; 1 syncwarp/step.
// ---------------------------------------------------------------------------
__global__ void __launch_bounds__(32, 1) recurrence_kernel(
    const __half* __restrict__ Mg, __half* __restrict__ hs)
{
    __shared__ __align__(16) __half smh[8][32][40];
    __shared__ __align__(16) float hsm[2][32];
    const int j = threadIdx.x;
    const int b = blockIdx.x >> 4;
    const int h = blockIdx.x & 15;
    const __half* Mbh = Mg + ((size_t)h * BSROWS + (size_t)b * SEQ) * 1024;
    const uint32_t sbase = smem_u32(&smh[0][0][0]) + (uint32_t)j * 80;

    // preload tiles 0..6 into stages 0..6
#pragma unroll
    for (int t = 0; t < 7; t++) {
        const __half* src = Mbh + (size_t)t * 1024 + j * 32;
        const uint32_t dst = sbase + (uint32_t)t * 2560;
#pragma unroll
        for (int c = 0; c < 4; c++) cp16(dst + c * 16, src + c * 8);
        asm volatile("cp.async.commit_group;");
    }
    hsm[0][j] = 0.17677669529663688f;   // 1/sqrt(32)
    __syncwarp();

    __half* hsb = hs + ((size_t)b * SEQ) * 512 + h * 32 + j;

    for (int s = 0; s < SEQ; ++s) {
        if (s + 7 < SEQ) {
            const __half* src = Mbh + (size_t)(s + 7) * 1024 + j * 32;
            const uint32_t dst = sbase + (uint32_t)((s + 7) & 7) * 2560;
#pragma unroll
            for (int c = 0; c < 4; c++) cp16(dst + c * 16, src + c * 8);
        }
        asm volatile("cp.async.commit_group;");
        asm volatile("cp.async.wait_group 7;");

        // vectorized row read: 4x LDS.128 (row is 16B-aligned: j*80)
        uint4 q0, q1, q2, q3;
        {
            const uint4* p = (const uint4*)&smh[s & 7][j][0];
            q0 = p[0]; q1 = p[1]; q2 = p[2]; q3 = p[3];
        }
        uint4 qq[4] = {q0, q1, q2, q3};
        const __half2* row2 = (const __half2*)qq;

        const float* hv = hsm[s & 1];
        float a0 = 0.f, a1 = 0.f, a2 = 0.f, a3 = 0.f;
#pragma unroll
        for (int c = 0; c < 8; c++) {
            float2 m0 = __half22float2(row2[2 * c]);
            float2 m1 = __half22float2(row2[2 * c + 1]);
            float4 hh = *(const float4*)&hv[c * 4];
            a0 = fmaf(hh.x, m0.x, a0);
            a1 = fmaf(hh.y, m0.y, a1);
            a2 = fmaf(hh.z, m1.x, a2);
            a3 = fmaf(hh.w, m1.y, a3);
        }
        float r = tanh_fast((a0 + a1) + (a2 + a3));
        hsm[(s + 1) & 1][j] = r;
        hsb[(size_t)s * 512] = __float2half(r);
        __syncwarp();
    }
}

// ---------------------------------------------------------------------------
// Launch
// ---------------------------------------------------------------------------
extern "C" void kernel_launch(void* const* d_in, const int* in_sizes, int n_in,
                              void* d_out, int out_size)
{
    const float* x     = (const float*)d_in[0];
    const float* ln1_g = (const float*)d_in[1];
    const float* ln1_b = (const float*)d_in[2];
    const float* W_in  = (const float*)d_in[3];
    const float* b_in  = (const float*)d_in[4];
    const float* A     = (const float*)d_in[5];
    const float* W_out = (const float*)d_in[6];
    const float* b_out = (const float*)d_in[7];
    const float* ln2_g = (const float*)d_in[8];
    const float* ln2_b = (const float*)d_in[9];
    const float* W1    = (const float*)d_in[10];
    const float* b1    = (const float*)d_in[11];
    const float* W2    = (const float*)d_in[12];
    const float* b2    = (const float*)d_in[13];
    float* out = (float*)d_out;

    float *x2;
    __half *lnh, *vh, *a2h, *Mh, *hsh, *ffnh, *winh, *wouth, *w1h, *w2h;
    cudaGetSymbolAddress((void**)&lnh,   g_lnh);
    cudaGetSymbolAddress((void**)&vh,    g_vh);
    cudaGetSymbolAddress((void**)&a2h,   g_a2h);
    cudaGetSymbolAddress((void**)&Mh,    g_Mh);
    cudaGetSymbolAddress((void**)&hsh,   g_hsh);
    cudaGetSymbolAddress((void**)&x2,    g_x2);
    cudaGetSymbolAddress((void**)&ffnh,  g_ffnh);
    cudaGetSymbolAddress((void**)&winh,  g_winh);
    cudaGetSymbolAddress((void**)&wouth, g_wouth);
    cudaGetSymbolAddress((void**)&w1h,   g_w1h);
    cudaGetSymbolAddress((void**)&w2h,   g_w2h);

    cudaFuncSetAttribute((const void*)(hgemm<0, __half>), cudaFuncAttributeMaxDynamicSharedMemorySize, HSMEM_BYTES);
    cudaFuncSetAttribute((const void*)(hgemm<1, __half>), cudaFuncAttributeMaxDynamicSharedMemorySize, HSMEM_BYTES);
    cudaFuncSetAttribute((const void*)(hgemm<5, __half>), cudaFuncAttributeMaxDynamicSharedMemorySize, HSMEM_BYTES);
    cudaFuncSetAttribute((const void*)(hgemm<3, float>),  cudaFuncAttributeMaxDynamicSharedMemorySize, HSMEM_BYTES);

    // 1) A rearrange -> fp16
    prep_A_kernel<<<4096, 256>>>(A, a2h);

    // 2) all weight transposes -> fp16 [N][K]
    tconv_all_kernel<<<9728, dim3(32, 8)>>>(W1, w1h, W2, w2h, W_in, winh, W_out, wouth);

    // 3) LN1 -> fp16
    ln_h_kernel<<<BSROWS, 256>>>(x, ln1_g, ln1_b, lnh);

    // 4) v = ln @ W_in + b_in   [8192 x 1024 x 1024]  fp16 out
    hgemm<1, __half><<<dim3(8, 64, 1), 512, HSMEM_BYTES>>>(
        lnh, winh, vh, b_in, nullptr, DIM, DIM, DIM, DIM, 0, 0, 0);

    // 5) M[h] = v[:, h*64:(h+1)*64] @ A2[h]^T   16 heads, [8192 x 1024 x 64]
    hgemm<0, __half><<<dim3(8, 64, NH), 512, HSMEM_BYTES>>>(
        vh, a2h, Mh, nullptr, nullptr, 64, DIM, 64, 1024,
        (size_t)64, (size_t)65536, (size_t)BSROWS * 1024);

    // 6) sequential recurrence -> hs (fp16)
    recurrence_kernel<<<64, 32>>>(Mh, hsh);

    // 7) x2 = x + hs @ W_out + b_out   [8192 x 1024 x 512]  fp32 out
    hgemm<3, float><<<dim3(8, 64, 1), 512, HSMEM_BYTES>>>(
        hsh, wouth, x2, b_out, x, 512, 512, 512, DIM, 0, 0, 0);

    // 8) LN2 -> fp16
    ln_h_kernel<<<BSROWS, 256>>>(x2, ln2_g, ln2_b, lnh);

    // 9) ffn = gelu(lnh @ W1 + b1)  [8192 x 4096 x 1024]  fp16 out
    hgemm<5, __half><<<dim3(32, 64, 1), 512, HSMEM_BYTES>>>(
        lnh, w1h, ffnh, b1, nullptr, DIM, DIM, DIM, DFF, 0, 0, 0);

    // 10) out = x2 + ffnh @ W2 + b2  [8192 x 1024 x 4096]  fp32 out
    hgemm<3, float><<<dim3(8, 64, 1), 512, HSMEM_BYTES>>>(
        ffnh, w2h, out, b2, x2, DFF, DFF, DFF, DIM, 0, 0, 0);
}

// round 17
// speedup vs baseline: 1.0087x; 1.0087x over previous
#include <cuda_runtime.h>
#include <cuda_fp16.h>
#include <math.h>
#include <cstdint>

#define BSROWS 8192
#define SEQ    2048
#define DIM    1024
#define NH     16
#define DFF    4096

// ---------------------------------------------------------------------------
// Scratch (device globals)
// ---------------------------------------------------------------------------
__device__ __half g_lnh  [8388608];    // LN output (reused LN1/LN2)
__device__ __half g_vh   [8388608];    // v = LN1@W_in + b_in
__device__ __half g_a2h  [1048576];    // A rearranged [h][j*32+i][p]
__device__ __half g_hsh  [4194304];    // recurrence out [bs][H*DH]
__device__ float  g_x2   [8388608];    // x + hs@W_out + b_out (fp32 residual)
__device__ __half g_ffnh [33554432];   // GELU(LN2@W1+b1)
__device__ __half g_winh [1048576];    // W_in^T  [1024][1024]
__device__ __half g_wouth[524288];     // W_out^T [1024][512]
__device__ __half g_w1h  [4194304];    // W1^T    [4096][1024]
__device__ __half g_w2h  [4194304];    // W2^T    [1024][4096]

// ---------------------------------------------------------------------------
// Helpers
// ---------------------------------------------------------------------------
__device__ __forceinline__ uint32_t smem_u32(const void* p) {
    return (uint32_t)__cvta_generic_to_shared(p);
}
__device__ __forceinline__ float gelu_exact(float x) {
    return 0.5f * x * (1.0f + erff(x * 0.70710678118654752f));
}
__device__ __forceinline__ void cp16(uint32_t dst, const void* src) {
    asm volatile("cp.async.cg.shared.global [%0], [%1], 16;" :: "r"(dst), "l"(src));
}
__device__ __forceinline__ float tanh_fast(float x) {
    float r;
    asm("tanh.approx.f32 %0, %1;" : "=f"(r) : "f"(x));
    return r;
}
__device__ __forceinline__ void mma_f16(float* d, const uint32_t* a, const uint32_t* b) {
    asm volatile(
        "mma.sync.aligned.m16n8k16.row.col.f32.f16.f16.f32 "
        "{%0,%1,%2,%3}, {%4,%5,%6,%7}, {%8,%9}, {%0,%1,%2,%3};"
        : "+f"(d[0]), "+f"(d[1]), "+f"(d[2]), "+f"(d[3])
        : "r"(a[0]), "r"(a[1]), "r"(a[2]), "r"(a[3]),
          "r"(b[0]), "r"(b[1]));
}
__device__ __forceinline__ void ldsm4(uint32_t& r0, uint32_t& r1, uint32_t& r2,
                                      uint32_t& r3, uint32_t addr) {
    asm volatile("ldmatrix.sync.aligned.m8n8.x4.shared.b16 {%0,%1,%2,%3}, [%4];"
                 : "=r"(r0), "=r"(r1), "=r"(r2), "=r"(r3) : "r"(addr));
}

// ---------------------------------------------------------------------------
// prep: A[h][i][p][j] -> a2h[h][j*32+i][p]  (fp16)
// ---------------------------------------------------------------------------
__global__ void prep_A_kernel(const float* __restrict__ A, __half* __restrict__ A2) {
    int idx = blockIdx.x * 256 + threadIdx.x;
    int j = idx & 31;
    int p = (idx >> 5) & 63;
    int i = (idx >> 11) & 31;
    int h = idx >> 16;
    A2[(size_t)h * 65536 + (size_t)(j * 32 + i) * 64 + p] = __float2half(A[idx]);
}

// ---------------------------------------------------------------------------
// Merged weight transposes (fp32 [R][C] -> fp16 [C][R]).
// ---------------------------------------------------------------------------
__device__ __forceinline__ void ttile(const float* __restrict__ in,
                                      __half* __restrict__ out,
                                      int R, int C, int bx, int by) {
    __shared__ float t[32][33];
    int tx = threadIdx.x, ty = threadIdx.y;
    int x0 = bx * 32, y0 = by * 32;
#pragma unroll
    for (int j = 0; j < 32; j += 8)
        t[ty + j][tx] = in[(size_t)(y0 + ty + j) * C + x0 + tx];
    __syncthreads();
#pragma unroll
    for (int j = 0; j < 32; j += 8)
        out[(size_t)(x0 + ty + j) * R + y0 + tx] = __float2half(t[tx][ty + j]);
}

__global__ void tconv_all_kernel(const float* __restrict__ W1, __half* __restrict__ w1h,
                                 const float* __restrict__ W2, __half* __restrict__ w2h,
                                 const float* __restrict__ Wi, __half* __restrict__ wih,
                                 const float* __restrict__ Wo, __half* __restrict__ woh)
{
    int t = blockIdx.x;
    if (t < 4096)        ttile(W1, w1h, 1024, 4096, t & 127, t >> 7);
    else if (t < 8192)   { t -= 4096; ttile(W2, w2h, 4096, 1024, t & 31, t >> 5); }
    else if (t < 9216)   { t -= 8192; ttile(Wi, wih, 1024, 1024, t & 31, t >> 5); }
    else                 { t -= 9216; ttile(Wo, woh, 512, 1024, t & 31, t >> 5); }
}

// ---------------------------------------------------------------------------
// LayerNorm (fp32 in, fp16 out).
// ---------------------------------------------------------------------------
__global__ void ln_h_kernel(const float* __restrict__ x, const float* __restrict__ g,
                            const float* __restrict__ b, __half* __restrict__ y) {
    int row = blockIdx.x;
    int tid = threadIdx.x;
    const float* xr = x + (size_t)row * DIM;
    float v[4];
    float s = 0.f, sq = 0.f;
#pragma unroll
    for (int i = 0; i < 4; i++) {
        v[i] = xr[tid + i * 256];
        s  += v[i];
        sq += v[i] * v[i];
    }
#pragma unroll
    for (int o = 16; o > 0; o >>= 1) {
        s  += __shfl_xor_sync(0xffffffffu, s,  o);
        sq += __shfl_xor_sync(0xffffffffu, sq, o);
    }
    __shared__ float ss[8], sqq[8];
    int w = tid >> 5, l = tid & 31;
    if (l == 0) { ss[w] = s; sqq[w] = sq; }
    __syncthreads();
    if (w == 0) {
        s  = (l < 8) ? ss[l]  : 0.f;
        sq = (l < 8) ? sqq[l] : 0.f;
#pragma unroll
        for (int o = 4; o > 0; o >>= 1) {
            s  += __shfl_xor_sync(0xffffffffu, s,  o);
            sq += __shfl_xor_sync(0xffffffffu, sq, o);
        }
        if (l == 0) { ss[0] = s; sqq[0] = sq; }
    }
    __syncthreads();
    s = ss[0]; sq = sqq[0];
    float mean = s * (1.0f / DIM);
    float var  = sq * (1.0f / DIM) - mean * mean;
    float rstd = rsqrtf(var + 1e-5f);
    __half* yr = y + (size_t)row * DIM;
#pragma unroll
    for (int i = 0; i < 4; i++) {
        int c = tid + i * 256;
        yr[c] = __float2half((v[i] - mean) * rstd * g[c] + b[c]);
    }
}

// ---------------------------------------------------------------------------
// fp16 warp-MMA GEMM — R15 configuration (best measured): 512 threads,
// warp tile 32x32, 2 CTAs/SM (64 regs), CTA tile 128x128, BK=32, 3-stage
// cp.async, ldmatrix fragments, mma.m16n8k16, fp32 accumulate.
// ---------------------------------------------------------------------------
#define HSMEM_BYTES 61440

template <int EPI, typename OT>
__global__ void __launch_bounds__(512, 2) hgemm(
    const __half* __restrict__ A, const __half* __restrict__ BT, OT* __restrict__ C,
    const float* __restrict__ bias, const float* __restrict__ res,
    int K, int lda, int ldb, int ldc,
    size_t batchA, size_t batchB, size_t batchC)
{
    extern __shared__ __half hsm[];
    __half* As = hsm;            // [3][128][40]
    __half* Bs = hsm + 15360;    // [3][128][40]

    A  += (size_t)blockIdx.z * batchA;
    BT += (size_t)blockIdx.z * batchB;
    C  += (size_t)blockIdx.z * batchC;

    const int tid = threadIdx.x;
    const int m0 = blockIdx.y * 128, n0 = blockIdx.x * 128;
    const int wid = tid >> 5, lane = tid & 31;
    const int wm = (wid >> 2) * 32;
    const int wn = (wid & 3) * 32;
    const int gq = lane >> 2, tg = lane & 3;

    const uint32_t sA = smem_u32(As);
    const uint32_t sB = smem_u32(Bs);

    const int row = tid >> 2, seg = tid & 3;

    auto loadA = [&](int st, int k0) {
        const __half* src = A + (size_t)(m0 + row) * lda + k0 + seg * 8;
        uint32_t dst = sA + (uint32_t)st * 10240 + (uint32_t)row * 80 + (uint32_t)seg * 16;
        cp16(dst, src);
    };
    auto loadB = [&](int st, int k0) {
        const __half* src = BT + (size_t)(n0 + row) * ldb + k0 + seg * 8;
        uint32_t dst = sB + (uint32_t)st * 10240 + (uint32_t)row * 80 + (uint32_t)seg * 16;
        cp16(dst, src);
    };

    const int arow_l = (lane & 7) | (((lane >> 3) & 1) << 3);
    const int aseg   = lane >> 4;
    const uint32_t aoffB = (uint32_t)(wm + arow_l) * 80 + (uint32_t)aseg * 16;
    const int brow_l = (lane & 7) + ((lane >> 4) << 3);
    const int bseg   = (lane >> 3) & 1;
    const uint32_t boffB = (uint32_t)(wn + brow_l) * 80 + (uint32_t)bseg * 16;

    float acc[2][4][4];
#pragma unroll
    for (int mi = 0; mi < 2; mi++)
#pragma unroll
        for (int ni = 0; ni < 4; ni++)
#pragma unroll
            for (int q = 0; q < 4; q++) acc[mi][ni][q] = 0.f;

    const int KT = K >> 5;
    loadA(0, 0);  loadB(0, 0);
    asm volatile("cp.async.commit_group;");
    loadA(1, 32); loadB(1, 32);
    asm volatile("cp.async.commit_group;");

    for (int kt = 0; kt < KT; ++kt) {
        const int buf = kt % 3;
        asm volatile("cp.async.wait_group 1;");
        __syncthreads();
        if (kt + 2 < KT) {
            const int st = (kt + 2) % 3;
            loadA(st, (kt + 2) * 32);
            loadB(st, (kt + 2) * 32);
        }
        asm volatile("cp.async.commit_group;");

        const uint32_t aB = sA + (uint32_t)buf * 10240 + aoffB;
        const uint32_t bB = sB + (uint32_t)buf * 10240 + boffB;
#pragma unroll
        for (int kk = 0; kk < 32; kk += 16) {
            uint32_t a[2][4], b[4][2];
#pragma unroll
            for (int mi = 0; mi < 2; mi++)
                ldsm4(a[mi][0], a[mi][1], a[mi][2], a[mi][3],
                      aB + (uint32_t)mi * (16 * 80) + (uint32_t)kk * 2);
#pragma unroll
            for (int p = 0; p < 2; p++)
                ldsm4(b[2 * p][0], b[2 * p][1], b[2 * p + 1][0], b[2 * p + 1][1],
                      bB + (uint32_t)p * (16 * 80) + (uint32_t)kk * 2);
#pragma unroll
            for (int mi = 0; mi < 2; mi++)
#pragma unroll
                for (int ni = 0; ni < 4; ni++)
                    mma_f16(acc[mi][ni], a[mi], b[ni]);
        }
    }

#pragma unroll
    for (int mi = 0; mi < 2; mi++) {
        const int r0 = m0 + wm + mi * 16 + gq;
#pragma unroll
        for (int ni = 0; ni < 4; ni++) {
            const int c = n0 + wn + ni * 8 + 2 * tg;
            float2 v01 = make_float2(acc[mi][ni][0], acc[mi][ni][1]);
            float2 v23 = make_float2(acc[mi][ni][2], acc[mi][ni][3]);
            if (EPI & 1) {
                float2 bv = *(const float2*)(bias + c);
                v01.x += bv.x; v01.y += bv.y;
                v23.x += bv.x; v23.y += bv.y;
            }
            if (EPI & 4) {
                v01.x = gelu_exact(v01.x); v01.y = gelu_exact(v01.y);
                v23.x = gelu_exact(v23.x); v23.y = gelu_exact(v23.y);
            }
            size_t off0 = (size_t)r0 * ldc + c;
            size_t off1 = (size_t)(r0 + 8) * ldc + c;
            if (EPI & 2) {
                float2 q0 = *(const float2*)(res + off0);
                float2 q1 = *(const float2*)(res + off1);
                v01.x += q0.x; v01.y += q0.y;
                v23.x += q1.x; v23.y += q1.y;
            }
            if constexpr (sizeof(OT) == 2) {
                *(__half2*)((__half*)C + off0) = __floats2half2_rn(v01.x, v01.y);
                *(__half2*)((__half*)C + off1) = __floats2half2_rn(v23.x, v23.y);
            } else {
                *(float2*)((float*)C + off0) = v01;
                *(float2*)((float*)C + off1) = v23;
            }
        }
    }
}

// ---------------------------------------------------------------------------
// FUSED gemm_M + recurrence. One CTA per (b,h) chain (64 CTAs, 1/SM).
// 288 threads: warps 0..7 = producers (HMMA M for 16 steps ahead, into a
// double-buffered smem stage), warp 8 = consumer (R10 serial chain, reading
// M from smem). A2[h] resident in smem (ldmatrix-friendly 144B row stride).
// M accumulation order identical to the old hgemm<0> -> bit-identical M.
// Dyn smem: A2s 1024x72h @0 (147456B), Ms 2x16x1032h @147456 (66048B),
//           vs 2x16x72h @213504 (4608B). Total 218112B.
// ---------------------------------------------------------------------------
#define FUSED_SMEM 218112

__global__ void __launch_bounds__(288, 1) fused_mps_kernel(
    const __half* __restrict__ vg, const __half* __restrict__ a2h,
    __half* __restrict__ hs)
{
    extern __shared__ __half fsm[];
    __shared__ __align__(16) float hrec[2][32];

    __half* A2s = fsm;                       // [1024][72]
    __half* Ms  = fsm + 73728;               // [2][16][1032]  (147456 B offset)
    __half* Vs  = fsm + 106752;              // [2][16][72]    (213504 B offset)

    const int tid = threadIdx.x;
    const int wid = tid >> 5, lane = tid & 31;
    const int b = blockIdx.x >> 4;
    const int h = blockIdx.x & 15;
    const bool producer = (wid < 8);

    const uint32_t sA2 = smem_u32(A2s);
    const uint32_t sVs = smem_u32(Vs);

    // fragment lane offsets (same proven maps as hgemm)
    const int arow_l = (lane & 7) | (((lane >> 3) & 1) << 3);
    const int aseg   = lane >> 4;
    const int brow_l = (lane & 7) + ((lane >> 4) << 3);
    const int bseg   = (lane >> 3) & 1;
    const int gq = lane >> 2, tg = lane & 3;
    const int n0w = wid * 128;               // producer n-range

    // ---- prologue: A2[h] -> smem (all threads), v group 0 (producers) ----
    const __half* a2g = a2h + (size_t)h * 65536;
    for (int idx = tid; idx < 8192; idx += 288) {
        int r = idx >> 3, c = idx & 7;
        cp16(sA2 + (uint32_t)r * 144 + (uint32_t)c * 16, a2g + r * 64 + c * 8);
    }
    const __half* vbase = vg + ((size_t)b * SEQ) * 1024 + h * 64;
    if (tid < 128) {
        int st = tid >> 3, c = tid & 7;
        cp16(sVs + (uint32_t)st * 144 + (uint32_t)c * 16,
             vbase + (size_t)st * 1024 + c * 8);
    }
    asm volatile("cp.async.commit_group;");
    asm volatile("cp.async.wait_group 0;");
    if (wid == 8) hrec[0][lane] = 0.17677669529663688f;   // 1/sqrt(32)
    __syncthreads();

    // producer: compute one 16-step group from Vs[vbuf] into Ms[mbuf]
    auto compute_group = [&](int vbuf, int mbuf) {
        float acc[8][2][4];
#pragma unroll
        for (int p = 0; p < 8; p++)
#pragma unroll
            for (int t = 0; t < 2; t++)
#pragma unroll
                for (int q = 0; q < 4; q++) acc[p][t][q] = 0.f;
        const uint32_t vB = sVs + (uint32_t)vbuf * 2304
                          + (uint32_t)arow_l * 144 + (uint32_t)aseg * 16;
#pragma unroll
        for (int kk = 0; kk < 64; kk += 16) {
            uint32_t a[4];
            ldsm4(a[0], a[1], a[2], a[3], vB + (uint32_t)kk * 2);
#pragma unroll
            for (int p = 0; p < 8; p++) {
                uint32_t b0[2], b1[2];
                ldsm4(b0[0], b0[1], b1[0], b1[1],
                      sA2 + (uint32_t)(n0w + p * 16 + brow_l) * 144
                          + (uint32_t)bseg * 16 + (uint32_t)kk * 2);
                mma_f16(acc[p][0], a, b0);
                mma_f16(acc[p][1], a, b1);
            }
        }
        __half* mb = Ms + (size_t)mbuf * 16512;   // 16*1032 halves per buf
#pragma unroll
        for (int p = 0; p < 8; p++)
#pragma unroll
            for (int t = 0; t < 2; t++) {
                const int col = n0w + (2 * p + t) * 8 + 2 * tg;
                *(__half2*)(mb + (size_t)gq * 1032 + col) =
                    __floats2half2_rn(acc[p][t][0], acc[p][t][1]);
                *(__half2*)(mb + (size_t)(gq + 8) * 1032 + col) =
                    __floats2half2_rn(acc[p][t][2], acc[p][t][3]);
            }
    };

    if (producer) compute_group(0, 0);
    __syncthreads();

    __half* hsb = hs + ((size_t)b * SEQ) * 512 + h * 32 + lane;

    for (int g = 0; g < 128; ++g) {
        const int buf = g & 1;
        if (producer) {
            if (g + 1 < 128) {
                if (tid < 128) {
                    int st = tid >> 3, c = tid & 7;
                    cp16(sVs + (uint32_t)(buf ^ 1) * 2304
                             + (uint32_t)st * 144 + (uint32_t)c * 16,
                         vbase + (size_t)((g + 1) * 16 + st) * 1024 + c * 8);
                }
                asm volatile("cp.async.commit_group;");
                asm volatile("cp.async.wait_group 0;");
                asm volatile("bar.sync 1, 256;");
                compute_group(buf ^ 1, buf ^ 1);
            }
        } else {
            const __half* mb = Ms + (size_t)buf * 16512;
#pragma unroll 1
            for (int t = 0; t < 16; ++t) {
                const int s = g * 16 + t;
                const uint4* p4 = (const uint4*)(mb + (size_t)t * 1032 + lane * 32);
                uint4 qq[4] = {p4[0], p4[1], p4[2], p4[3]};
                const __half2* row2 = (const __half2*)qq;
                const float* hv = hrec[s & 1];
                float a0 = 0.f, a1 = 0.f, a2 = 0.f, a3 = 0.f;
#pragma unroll
                for (int c = 0; c < 8; c++) {
                    float2 m0 = __half22float2(row2[2 * c]);
                    float2 m1 = __half22float2(row2[2 * c + 1]);
                    float4 hh = *(const float4*)&hv[c * 4];
                    a0 = fmaf(hh.x, m0.x, a0);
                    a1 = fmaf(hh.y, m0.y, a1);
                    a2 = fmaf(hh.z, m1.x, a2);
                    a3 = fmaf(hh.w, m1.y, a3);
                }
                float r = tanh_fast((a0 + a1) + (a2 + a3));
                hrec[(s + 1) & 1][lane] = r;
                hsb[(size_t)s * 512] = __float2half(r);
                __syncwarp();
            }
        }
        __syncthreads();
    }
}

// ---------------------------------------------------------------------------
// Launch
// ---------------------------------------------------------------------------
extern "C" void kernel_launch(void* const* d_in, const int* in_sizes, int n_in,
                              void* d_out, int out_size)
{
    const float* x     = (const float*)d_in[0];
    const float* ln1_g = (const float*)d_in[1];
    const float* ln1_b = (const float*)d_in[2];
    const float* W_in  = (const float*)d_in[3];
    const float* b_in  = (const float*)d_in[4];
    const float* A     = (const float*)d_in[5];
    const float* W_out = (const float*)d_in[6];
    const float* b_out = (const float*)d_in[7];
    const float* ln2_g = (const float*)d_in[8];
    const float* ln2_b = (const float*)d_in[9];
    const float* W1    = (const float*)d_in[10];
    const float* b1    = (const float*)d_in[11];
    const float* W2    = (const float*)d_in[12];
    const float* b2    = (const float*)d_in[13];
    float* out = (float*)d_out;

    float *x2;
    __half *lnh, *vh, *a2h, *hsh, *ffnh, *winh, *wouth, *w1h, *w2h;
    cudaGetSymbolAddress((void**)&lnh,   g_lnh);
    cudaGetSymbolAddress((void**)&vh,    g_vh);
    cudaGetSymbolAddress((void**)&a2h,   g_a2h);
    cudaGetSymbolAddress((void**)&hsh,   g_hsh);
    cudaGetSymbolAddress((void**)&x2,    g_x2);
    cudaGetSymbolAddress((void**)&ffnh,  g_ffnh);
    cudaGetSymbolAddress((void**)&winh,  g_winh);
    cudaGetSymbolAddress((void**)&wouth, g_wouth);
    cudaGetSymbolAddress((void**)&w1h,   g_w1h);
    cudaGetSymbolAddress((void**)&w2h,   g_w2h);

    cudaFuncSetAttribute((const void*)(hgemm<1, __half>), cudaFuncAttributeMaxDynamicSharedMemorySize, HSMEM_BYTES);
    cudaFuncSetAttribute((const void*)(hgemm<5, __half>), cudaFuncAttributeMaxDynamicSharedMemorySize, HSMEM_BYTES);
    cudaFuncSetAttribute((const void*)(hgemm<3, float>),  cudaFuncAttributeMaxDynamicSharedMemorySize, HSMEM_BYTES);
    cudaFuncSetAttribute((const void*)fused_mps_kernel,   cudaFuncAttributeMaxDynamicSharedMemorySize, FUSED_SMEM);

    // 1) A rearrange -> fp16
    prep_A_kernel<<<4096, 256>>>(A, a2h);

    // 2) all weight transposes -> fp16 [N][K]
    tconv_all_kernel<<<9728, dim3(32, 8)>>>(W1, w1h, W2, w2h, W_in, winh, W_out, wouth);

    // 3) LN1 -> fp16
    ln_h_kernel<<<BSROWS, 256>>>(x, ln1_g, ln1_b, lnh);

    // 4) v = ln @ W_in + b_in   [8192 x 1024 x 1024]  fp16 out
    hgemm<1, __half><<<dim3(8, 64, 1), 512, HSMEM_BYTES>>>(
        lnh, winh, vh, b_in, nullptr, DIM, DIM, DIM, DIM, 0, 0, 0);

    // 5) FUSED: M on-the-fly (tensor cores) + sequential recurrence -> hs
    fused_mps_kernel<<<64, 288, FUSED_SMEM>>>(vh, a2h, hsh);

    // 6) x2 = x + hs @ W_out + b_out   [8192 x 1024 x 512]  fp32 out
    hgemm<3, float><<<dim3(8, 64, 1), 512, HSMEM_BYTES>>>(
        hsh, wouth, x2, b_out, x, 512, 512, 512, DIM, 0, 0, 0);

    // 7) LN2 -> fp16
    ln_h_kernel<<<BSROWS, 256>>>(x2, ln2_g, ln2_b, lnh);

    // 8) ffn = gelu(lnh @ W1 + b1)  [8192 x 4096 x 1024]  fp16 out
    hgemm<5, __half><<<dim3(32, 64, 1), 512, HSMEM_BYTES>>>(
        lnh, w1h, ffnh, b1, nullptr, DIM, DIM, DIM, DFF, 0, 0, 0);

    // 9) out = x2 + ffnh @ W2 + b2  [8192 x 1024 x 4096]  fp32 out
    hgemm<3, float><<<dim3(8, 64, 1), 512, HSMEM_BYTES>>>(
        ffnh, w2h, out, b2, x2, DFF, DFF, DFF, DIM, 0, 0, 0);
}